// round 6
// baseline (speedup 1.0000x reference)
#include <cuda_runtime.h>

#define TPB    384        // one thread per float4 of a 1536-float row
#define BAND   16         // output rows per block
#define HH     384
#define ROWF   1536       // W*C floats per row
#define NBANDS (HH / BAND)

static __device__ __forceinline__ int hrefl(int h) {
    // reflect-101 along height; used only for h in [-2, HH+1]
    h = (h < 0) ? -h : h;
    return (h >= HH) ? (2 * HH - 2 - h) : h;
}

// Gaussian taps for ksize=5, sigma=1.1 (OpenCV default), normalized.
#define C0 0.07076630f    /* w[0] = w[4] */
#define C1 0.24446028f    /* w[1] = w[3] */
#define C2 0.36954642f    /* w[2]        */

struct Raw { float4 C; float h0, h1, h2, h3, h4, h5; };

// LOAD STAGE: this thread's float4 (flats 4t..4t+3) of row h, plus the
// cross-warp halo floats for warp-edge lanes (pure loads, no shuffles).
static __device__ __forceinline__ Raw load_raw(
    const float* __restrict__ ib, int h, int t, int lane)
{
    const float* __restrict__ rp = ib + (long)hrefl(h) * ROWF + 4 * t;
    Raw r;
    r.C = *(const float4*)rp;
    if (lane == 0 && t >= 2) {             // e0..e5 = flats 4t-6 .. 4t-1
        float2 a = *(const float2*)(rp - 6);
        float4 b = *(const float4*)(rp - 4);
        r.h0 = a.x; r.h1 = a.y; r.h2 = b.x; r.h3 = b.y; r.h4 = b.z; r.h5 = b.w;
    } else if (lane == 1 && t >= 2) {      // e0,e1 = flats 4t-6, 4t-5
        float2 a = *(const float2*)(rp - 6);
        r.h0 = a.x; r.h1 = a.y;
    } else if (lane == 31 && t <= TPB - 3) { // e10..e15 = flats 4t+4 .. 4t+9
        float4 b = *(const float4*)(rp + 4);
        float2 a = *(const float2*)(rp + 8);
        r.h0 = b.x; r.h1 = b.y; r.h2 = b.z; r.h3 = b.w; r.h4 = a.x; r.h5 = a.y;
    } else if (lane == 30 && t <= TPB - 3) { // e14,e15 = flats 4t+8, 4t+9
        float2 a = *(const float2*)(rp + 8);
        r.h0 = a.x; r.h1 = a.y;
    }
    return r;
}

// COMPUTE STAGE: horizontal blur of 4 floats; halo via lane shuffles,
// warp edges via r.h*, image width edges via register permutation.
static __device__ __forceinline__ float4 hb_compute(const Raw& r, int t, int lane)
{
    const float4 Cb = r.C;

    // e[k] = flat(4t - 6 + k), k = 0..15 ; e6..e9 = Cb.
    float e2  = __shfl_up_sync(0xffffffffu, Cb.x, 1);
    float e3  = __shfl_up_sync(0xffffffffu, Cb.y, 1);
    float e4  = __shfl_up_sync(0xffffffffu, Cb.z, 1);
    float e5  = __shfl_up_sync(0xffffffffu, Cb.w, 1);
    float e0  = __shfl_up_sync(0xffffffffu, Cb.z, 2);
    float e1  = __shfl_up_sync(0xffffffffu, Cb.w, 2);
    float e10 = __shfl_down_sync(0xffffffffu, Cb.x, 1);
    float e11 = __shfl_down_sync(0xffffffffu, Cb.y, 1);
    float e12 = __shfl_down_sync(0xffffffffu, Cb.z, 1);
    float e13 = __shfl_down_sync(0xffffffffu, Cb.w, 1);
    float e14 = __shfl_down_sync(0xffffffffu, Cb.x, 2);
    float e15 = __shfl_down_sync(0xffffffffu, Cb.y, 2);

    if (lane == 0 && t >= 2) {
        e0 = r.h0; e1 = r.h1; e2 = r.h2; e3 = r.h3; e4 = r.h4; e5 = r.h5;
    } else if (lane == 1 && t >= 2) {
        e0 = r.h0; e1 = r.h1;
    }
    if (lane == 31 && t <= TPB - 3) {
        e10 = r.h0; e11 = r.h1; e12 = r.h2; e13 = r.h3; e14 = r.h4; e15 = r.h5;
    } else if (lane == 30 && t <= TPB - 3) {
        e14 = r.h0; e15 = r.h1;
    }

    // Image width edges (reflect-101 folds to a permutation of held values).
    if (t == 0) {          // flats -6..-1 -> {6,7,8,3,4,5}
        e0 = e12; e1 = e13; e2 = e14; e3 = Cb.w; e4 = e10; e5 = e11;
    } else if (t == 1) {   // flats -2,-1 -> {4,5} = own .x,.y
        e0 = Cb.x; e1 = Cb.y;
    }
    if (t == TPB - 1) {    // flats 1536..1541 -> {1530,1531,1532,1527,1528,1529}
        e10 = e4; e11 = e5; e12 = Cb.x; e13 = e1; e14 = e2; e15 = e3;
    } else if (t == TPB - 2) { // flats 1536,1537 -> own .z,.w
        e14 = Cb.z; e15 = Cb.w;
    }

    // Horizontal taps at flat offsets {-6,-3,0,+3,+6}.
    float4 o;
    o.x = C0 * (e0 + e12) + C1 * (e3   + Cb.w) + C2 * Cb.x;
    o.y = C0 * (e1 + e13) + C1 * (e4   + e10)  + C2 * Cb.y;
    o.z = C0 * (e2 + e14) + C1 * (e5   + e11)  + C2 * Cb.z;
    o.w = C0 * (e3 + e15) + C1 * (Cb.x + e12)  + C2 * Cb.w;
    return o;
}

__global__ void __launch_bounds__(TPB, 3)
gauss5_kernel(const float* __restrict__ x, float* __restrict__ y)
{
    const int t    = threadIdx.x;
    const int lane = t & 31;
    const int h0   = blockIdx.x * BAND;
    const long img = blockIdx.y;

    const float* __restrict__ ib = x + img * (long)(HH * ROWF);
    float*       __restrict__ ob = y + img * (long)(HH * ROWF) + 4 * t;

    // Prologue: 4 horizontally-blurred rows + raw row h0+2 (compute deferred).
    float4 w0 = hb_compute(load_raw(ib, h0 - 2, t, lane), t, lane);
    float4 w1 = hb_compute(load_raw(ib, h0 - 1, t, lane), t, lane);
    float4 w2 = hb_compute(load_raw(ib, h0,     t, lane), t, lane);
    float4 w3 = hb_compute(load_raw(ib, h0 + 1, t, lane), t, lane);
    Raw cur = load_raw(ib, h0 + 2, t, lane);

    #pragma unroll 4
    for (int r = 0; r < BAND; r++) {
        // Next row's loads issue before this row's dependent shuffle/FMA work.
        Raw nxt = load_raw(ib, h0 + r + 3, t, lane);

        float4 w4 = hb_compute(cur, t, lane);

        // Vertical pass (symmetric taps), thread-private.
        float4 o;
        o.x = C0 * (w0.x + w4.x) + C1 * (w1.x + w3.x) + C2 * w2.x;
        o.y = C0 * (w0.y + w4.y) + C1 * (w1.y + w3.y) + C2 * w2.y;
        o.z = C0 * (w0.z + w4.z) + C1 * (w1.z + w3.z) + C2 * w2.z;
        o.w = C0 * (w0.w + w4.w) + C1 * (w1.w + w3.w) + C2 * w2.w;

        *(float4*)(ob + (long)(h0 + r) * ROWF) = o;

        w0 = w1; w1 = w2; w2 = w3; w3 = w4;
        cur = nxt;
    }
}

extern "C" void kernel_launch(void* const* d_in, const int* in_sizes, int n_in,
                              void* d_out, int out_size)
{
    const float* x = (const float*)d_in[0];
    float* y = (float*)d_out;
    const int batch = in_sizes[0] / (HH * ROWF);   // 64
    dim3 grid(NBANDS, batch);
    gauss5_kernel<<<grid, TPB>>>(x, y);
}

// round 7
// speedup vs baseline: 1.3394x; 1.3394x over previous
#include <cuda_runtime.h>

#define TPB    96         // threads per block; each owns 8 floats (half a row)
#define NCOLS  192        // thread-columns per full row (1536/8)
#define BAND   16         // output rows per block
#define HH     384
#define ROWF   1536       // W*C floats per row
#define NBANDS (HH / BAND)

static __device__ __forceinline__ int hrefl(int h) {
    // reflect-101 along height; used only for h in [-2, HH+1]
    h = (h < 0) ? -h : h;
    return (h >= HH) ? (2 * HH - 2 - h) : h;
}

// Gaussian taps for ksize=5, sigma=1.1 (OpenCV default), normalized.
#define C0 0.07076630f    /* w[0] = w[4] */
#define C1 0.24446028f    /* w[1] = w[3] */
#define C2 0.36954642f    /* w[2]        */

struct F8  { float v[8]; };
struct Raw { float4 C, D; float e0, e1, e2, e3, e4, e5; };

// LOAD STAGE: this thread's 8 floats (flats 8g..8g+7) of row h, plus the
// 6-float cross-warp halo for warp-edge lanes. Pure loads, no shuffles.
static __device__ __forceinline__ Raw load_raw(
    const float* __restrict__ ib, int h, int g, int lane)
{
    const float* __restrict__ rp = ib + (long)hrefl(h) * ROWF + 8 * g;
    Raw r;
    r.C = *(const float4*)(rp);       // flats 8g   .. 8g+3
    r.D = *(const float4*)(rp + 4);   // flats 8g+4 .. 8g+7
    if (lane == 0 && g > 0) {         // left halo: flats 8g-6 .. 8g-1
        float2 a = *(const float2*)(rp - 6);
        float4 b = *(const float4*)(rp - 4);
        r.e0 = a.x; r.e1 = a.y; r.e2 = b.x; r.e3 = b.y; r.e4 = b.z; r.e5 = b.w;
    } else if (lane == 31 && g < NCOLS - 1) {  // right halo: flats 8g+8 .. 8g+13
        float4 b = *(const float4*)(rp + 8);
        float2 a = *(const float2*)(rp + 12);
        r.e0 = b.x; r.e1 = b.y; r.e2 = b.z; r.e3 = b.w; r.e4 = a.x; r.e5 = a.y;
    }
    return r;
}

// COMPUTE STAGE: horizontal blur via intra-warp shuffles; warp edges use the
// prefetched r.e*; image width edges fold reflect-101 into a permutation.
static __device__ __forceinline__ F8 hb_compute(const Raw& r, int g, int lane)
{
    const float4 Cb = r.C, Db = r.D;

    // e[k] = flat(8g - 6 + k), k = 0..19
    float e0  = __shfl_up_sync(0xffffffffu, Cb.z, 1);
    float e1  = __shfl_up_sync(0xffffffffu, Cb.w, 1);
    float e2  = __shfl_up_sync(0xffffffffu, Db.x, 1);
    float e3  = __shfl_up_sync(0xffffffffu, Db.y, 1);
    float e4  = __shfl_up_sync(0xffffffffu, Db.z, 1);
    float e5  = __shfl_up_sync(0xffffffffu, Db.w, 1);
    float e14 = __shfl_down_sync(0xffffffffu, Cb.x, 1);
    float e15 = __shfl_down_sync(0xffffffffu, Cb.y, 1);
    float e16 = __shfl_down_sync(0xffffffffu, Cb.z, 1);
    float e17 = __shfl_down_sync(0xffffffffu, Cb.w, 1);
    float e18 = __shfl_down_sync(0xffffffffu, Db.x, 1);
    float e19 = __shfl_down_sync(0xffffffffu, Db.y, 1);

    if (lane == 0 && g > 0) {
        e0 = r.e0; e1 = r.e1; e2 = r.e2; e3 = r.e3; e4 = r.e4; e5 = r.e5;
    }
    if (lane == 31 && g < NCOLS - 1) {
        e14 = r.e0; e15 = r.e1; e16 = r.e2; e17 = r.e3; e18 = r.e4; e19 = r.e5;
    }
    if (g == 0) {            // flats -6..-1 -> reflected {6,7,8,3,4,5}
        e0 = Db.z; e1 = Db.w; e2 = e14; e3 = Cb.w; e4 = Db.x; e5 = Db.y;
    }
    if (g == NCOLS - 1) {    // flats 1536..1541 -> {1530,1531,1532,1527,1528,1529}
        e14 = Cb.z; e15 = Cb.w; e16 = Db.x; e17 = e5; e18 = Cb.x; e19 = Cb.y;
    }

    const float e6 = Cb.x, e7 = Cb.y, e8 = Cb.z, e9 = Cb.w;
    const float e10 = Db.x, e11 = Db.y, e12 = Db.z, e13 = Db.w;

    // Horizontal taps at flat offsets {-6,-3,0,+3,+6}.
    F8 o;
    o.v[0] = C0 * (e0 + e12) + C1 * (e3  + e9)  + C2 * e6;
    o.v[1] = C0 * (e1 + e13) + C1 * (e4  + e10) + C2 * e7;
    o.v[2] = C0 * (e2 + e14) + C1 * (e5  + e11) + C2 * e8;
    o.v[3] = C0 * (e3 + e15) + C1 * (e6  + e12) + C2 * e9;
    o.v[4] = C0 * (e4 + e16) + C1 * (e7  + e13) + C2 * e10;
    o.v[5] = C0 * (e5 + e17) + C1 * (e8  + e14) + C2 * e11;
    o.v[6] = C0 * (e6 + e18) + C1 * (e9  + e15) + C2 * e12;
    o.v[7] = C0 * (e7 + e19) + C1 * (e10 + e16) + C2 * e13;
    return o;
}

__global__ void __launch_bounds__(TPB, 7)
gauss5_kernel(const float* __restrict__ x, float* __restrict__ y)
{
    const int t    = threadIdx.x;
    const int lane = t & 31;
    const int g    = blockIdx.x * TPB + t;   // global thread-column, 0..191
    const int h0   = blockIdx.y * BAND;
    const long img = blockIdx.z;

    const float* __restrict__ ib = x + img * (long)(HH * ROWF);
    float*       __restrict__ ob = y + img * (long)(HH * ROWF) + 8 * g;

    // Prologue: 4 horizontally-blurred rows + raw row h0+2 (compute deferred).
    F8 w0 = hb_compute(load_raw(ib, h0 - 2, g, lane), g, lane);
    F8 w1 = hb_compute(load_raw(ib, h0 - 1, g, lane), g, lane);
    F8 w2 = hb_compute(load_raw(ib, h0,     g, lane), g, lane);
    F8 w3 = hb_compute(load_raw(ib, h0 + 1, g, lane), g, lane);
    Raw cur = load_raw(ib, h0 + 2, g, lane);

    #pragma unroll 4
    for (int r = 0; r < BAND; r++) {
        // Next row's loads issue before this row's dependent shuffle/FMA work:
        // load-to-use distance = one full iteration (~2 rows in flight).
        Raw nxt = load_raw(ib, h0 + r + 3, g, lane);

        F8 w4 = hb_compute(cur, g, lane);

        // Vertical pass (symmetric taps), thread-private.
        float4 oa, obv;
        oa.x  = C0 * (w0.v[0] + w4.v[0]) + C1 * (w1.v[0] + w3.v[0]) + C2 * w2.v[0];
        oa.y  = C0 * (w0.v[1] + w4.v[1]) + C1 * (w1.v[1] + w3.v[1]) + C2 * w2.v[1];
        oa.z  = C0 * (w0.v[2] + w4.v[2]) + C1 * (w1.v[2] + w3.v[2]) + C2 * w2.v[2];
        oa.w  = C0 * (w0.v[3] + w4.v[3]) + C1 * (w1.v[3] + w3.v[3]) + C2 * w2.v[3];
        obv.x = C0 * (w0.v[4] + w4.v[4]) + C1 * (w1.v[4] + w3.v[4]) + C2 * w2.v[4];
        obv.y = C0 * (w0.v[5] + w4.v[5]) + C1 * (w1.v[5] + w3.v[5]) + C2 * w2.v[5];
        obv.z = C0 * (w0.v[6] + w4.v[6]) + C1 * (w1.v[6] + w3.v[6]) + C2 * w2.v[6];
        obv.w = C0 * (w0.v[7] + w4.v[7]) + C1 * (w1.v[7] + w3.v[7]) + C2 * w2.v[7];

        // Streaming stores: output is never re-read; keep L2 for halo rows.
        float* op = ob + (long)(h0 + r) * ROWF;
        __stcs((float4*)op,       oa);
        __stcs((float4*)(op + 4), obv);

        w0 = w1; w1 = w2; w2 = w3; w3 = w4;
        cur = nxt;
    }
}

extern "C" void kernel_launch(void* const* d_in, const int* in_sizes, int n_in,
                              void* d_out, int out_size)
{
    const float* x = (const float*)d_in[0];
    float* y = (float*)d_out;
    const int batch = in_sizes[0] / (HH * ROWF);   // 64
    dim3 grid(NCOLS / TPB, NBANDS, batch);
    gauss5_kernel<<<grid, TPB>>>(x, y);
}